// round 12
// baseline (speedup 1.0000x reference)
#include <cuda_runtime.h>
#include <cstdint>
#include <cstddef>

#define FULLMASK 0xFFFFFFFFu

namespace {
constexpr int      HW      = 4096;   // 64*64
constexpr unsigned KSEL    = 409;    // int(0.1 * 4096)
constexpr int      NTHREAD = 512;    // 2 rows x 256 threads
constexpr int      RWARPS  = 8;      // warps per row
constexpr int      TCAP    = 64;     // tie-list capacity for the selected bin
// Integer bins of width 2^14 over the magnitude key s = u<<1 (sign shifted out),
// covering |x| in [1.5, 1.75):
//   bm1 = (s >> 14) - (BINBASE+1);  counted bins are hist[1..255].
// "bin 0"  <=> |x| < 1.50024  -- uncounted; ~6 sigma below the 409th |x| of N(0,1)
// |x|>=1.75 -- counted in REGISTERS (c_hi), no atomics; threshold >= 1.75 is
//              ~4.6 sigma -> exact fallback if it happens.
// Boundaries are exact in key space: membership test is s - slo < 2^14.
constexpr int      BINBASE = 130560;      // 0x7F800000 >> 14
constexpr unsigned S_HI    = 0x7FC00000u; // key(1.75f) = bits(1.75)<<1
}

struct SmemRow {
    uint4    data[HW / 4];   // 16KB row stash (threads read only their own words)
    unsigned hist[256];
    unsigned wsum[RWARPS];
    unsigned whi[RWARPS];    // per-warp totals of c_hi (elements >= 1.75)
    unsigned tcnt;
    unsigned sel;            // selected bin (0xFFFFFFFF = none)
    unsigned r2;             // rank within selected bin
    unsigned Ts;             // threshold key (|x| bits << 1)
    unsigned inv_star;       // inverted-index cutoff for exact ties
    unsigned ts_[TCAP];
    unsigned tinv[TCAP];
};

// Row-wide total of per-thread count c (broadcast within the row).
// Barriers are block-wide; ALL 512 threads must call this together.
__device__ __forceinline__ unsigned row_total(SmemRow* R, unsigned c, int lane, int rwid) {
    c = __reduce_add_sync(FULLMASK, c);   // warp is entirely within one row
    __syncthreads();                      // protect wsum reuse across calls
    if (lane == 0) R->wsum[rwid] = c;
    __syncthreads();
    unsigned t = 0;
#pragma unroll
    for (int w = 0; w < RWARPS; w++) t += R->wsum[w];
    return t;
}

__global__ void __launch_bounds__(NTHREAD, 4)
topk_sparse_kernel(const float* __restrict__ x, float* __restrict__ y)
{
    __shared__ SmemRow sm[2];
    const int tid  = threadIdx.x;
    const int lane = tid & 31;
    const int rid  = tid >> 8;          // row within CTA (0 or 1)
    const int rt   = tid & 255;         // thread within row
    const int rwid = (tid >> 5) & 7;    // warp within row
    SmemRow* R = &sm[rid];

    const size_t rowbase = ((size_t)blockIdx.x * 2 + rid) * (HW / 4);
    const uint4* xin  = reinterpret_cast<const uint4*>(x) + rowbase;
    uint4*       yout = reinterpret_cast<uint4*>(y) + rowbase;
    // element (j,c) at linear idx 4*rt + 1024*j + c; inv = 4095 - idx
    const unsigned invbase = 4095u - ((unsigned)rt << 2);

    // ---- load row (4 x LDG.128, front-batched for MLP), stash to smem ----
    uint4 t0 = xin[rt];
    uint4 t1 = xin[rt + 256];
    uint4 t2 = xin[rt + 512];
    uint4 t3 = xin[rt + 768];

    R->hist[rt] = 0;
    if (rt == 0) { R->tcnt = 0; R->sel = 0xFFFFFFFFu; }

    R->data[rt]       = t0;
    R->data[rt + 256] = t1;
    R->data[rt + 512] = t2;
    R->data[rt + 768] = t3;
    __syncthreads();   // hist zeros visible before atomics (serves both rows)

    // ---- histogram pass from in-flight registers; upper tail in registers ----
    {
        unsigned uu[16] = { t0.x, t0.y, t0.z, t0.w,  t1.x, t1.y, t1.z, t1.w,
                            t2.x, t2.y, t2.z, t2.w,  t3.x, t3.y, t3.z, t3.w };
        unsigned c_hi = 0;
#pragma unroll
        for (int e = 0; e < 16; e++) {
            unsigned s = uu[e] << 1;
            c_hi += (s >= S_HI) ? 1u : 0u;                 // register-side tail count
            unsigned bm1 = (s >> 14) - (unsigned)(BINBASE + 1);
            if (bm1 < 255u)                                 // bin in [1,255]
                atomicAdd(&R->hist[bm1 + 1u], 1u);          // fire-and-forget ATOMS
        }
        c_hi = __reduce_add_sync(FULLMASK, c_hi);
        if (lane == 0) R->whi[rwid] = c_hi;
    }
    __syncthreads();

    // ---- rank offset from the register-counted tail (own row) ----
    unsigned chitot = 0;
#pragma unroll
    for (int w = 0; w < RWARPS; w++) chitot += R->whi[w];
    const bool fbhi = (chitot >= KSEL);          // threshold >= 1.75: fallback
    const unsigned r = KSEL - chitot;            // rank within [1.5, 1.75) bins

    // ---- descending cumulative scan over 256 bins (both rows in parallel) ----
    {
        int b = 255 - rt;
        unsigned cb = (b >= 1) ? R->hist[b] : 0u;   // bin 0 uncounted by design
        unsigned incl = cb;
#pragma unroll
        for (int d = 1; d < 32; d <<= 1) {
            unsigned n = __shfl_up_sync(FULLMASK, incl, d);
            if (lane >= d) incl += n;
        }
        if (lane == 31) R->wsum[rwid] = incl;
        __syncthreads();
#pragma unroll
        for (int w = 0; w < RWARPS - 1; w++)
            if (w < rwid) incl += R->wsum[w];
        unsigned excl = incl - cb;
        if (!fbhi && excl < r && r <= incl) { R->sel = (unsigned)b; R->r2 = r - excl; }
    }
    __syncthreads();

    // ---- retrieval: 2-op range test against the selected bin's key range ----
    // (if sel is invalid, slo is garbage but fb is taken and pushes are unused)
    const unsigned slo = (R->sel + (unsigned)BINBASE) << 14;
#pragma unroll
    for (int j = 0; j < 4; j++) {
        uint4 v = R->data[rt + j * 256];
        unsigned w4[4] = { v.x, v.y, v.z, v.w };
#pragma unroll
        for (int c = 0; c < 4; c++) {
            unsigned s = w4[c] << 1;
            if (s - slo < (1u << 14)) {            // exact bin membership
                unsigned pos = atomicAdd(&R->tcnt, 1u);
                if (pos < (unsigned)TCAP) {
                    R->ts_[pos]  = s;
                    R->tinv[pos] = invbase - (unsigned)((j << 10) + c);
                }
            }
        }
    }
    __syncthreads();

    // ---- fb decision: own row for fast path, block-uniform fbany for fallback ----
    const bool fbown = fbhi || (R->sel == 0xFFFFFFFFu) || (R->tcnt > (unsigned)TCAP);
    bool fbany;
    {
        unsigned ct0 = 0, ct1 = 0;
#pragma unroll
        for (int w = 0; w < RWARPS; w++) { ct0 += sm[0].whi[w]; ct1 += sm[1].whi[w]; }
        bool fb0 = (ct0 >= KSEL) || (sm[0].sel == 0xFFFFFFFFu) || (sm[0].tcnt > (unsigned)TCAP);
        bool fb1 = (ct1 >= KSEL) || (sm[1].sel == 0xFFFFFFFFu) || (sm[1].tcnt > (unsigned)TCAP);
        fbany = fb0 || fb1;
    }

    if (!fbown) {
        // ---- exact selection of rank r2 within the bin (ties by index) ----
        const unsigned m2 = R->tcnt;
        const unsigned r2 = R->r2;
        if ((unsigned)rt < m2) {
            unsigned si = R->ts_[rt], vi = R->tinv[rt];
            unsigned rank = 0;
            for (unsigned j = 0; j < m2; j++) {
                unsigned sj = R->ts_[j], vj = R->tinv[j];
                rank += (sj > si || (sj == si && vj > vi)) ? 1u : 0u;
            }
            if (rank == r2 - 1u) { R->Ts = si; R->inv_star = vi; }
        }
    }
    if (fbany) {
        // ---- exact fallback: bitwise binary search, BOTH rows run it (block-wide
        //      barriers inside row_total); result is exact for any row and
        //      overwrites whatever the fast path wrote. ~2e-5 probability. ----
        unsigned lo = 0;                       // s values are even; bit0 skipped
        for (int bit = 31; bit >= 1; bit--) {
            unsigned T = lo | (1u << bit);
            unsigned c = 0;
            for (int j = 0; j < 4; j++) {
                uint4 v = R->data[rt + j * 256];
                c += ((v.x << 1) >= T) + ((v.y << 1) >= T) + ((v.z << 1) >= T) + ((v.w << 1) >= T);
            }
            if (row_total(R, c, lane, rwid) >= KSEL) lo = T;
        }
        const unsigned Tsf = lo;               // exact KSEL-th largest key
        unsigned cgt = 0;
        for (int j = 0; j < 4; j++) {
            uint4 v = R->data[rt + j * 256];
            cgt += ((v.x << 1) > Tsf) + ((v.y << 1) > Tsf) + ((v.z << 1) > Tsf) + ((v.w << 1) > Tsf);
        }
        cgt = row_total(R, cgt, lane, rwid);
        const unsigned req = KSEL - cgt;       // >= 1 by construction
        unsigned vlo = 0;
        for (int bit = 11; bit >= 0; bit--) {
            unsigned V = vlo | (1u << bit);
            unsigned c = 0;
            for (int j = 0; j < 4; j++) {
                uint4 v = R->data[rt + j * 256];
                unsigned w4[4] = { v.x, v.y, v.z, v.w };
                for (int cc = 0; cc < 4; cc++) {
                    unsigned inv = invbase - (unsigned)((j << 10) + cc);
                    c += (((w4[cc] << 1) == Tsf) && inv >= V) ? 1u : 0u;
                }
            }
            if (row_total(R, c, lane, rwid) >= req) vlo = V;
        }
        if (rt == 0) { R->Ts = Tsf; R->inv_star = vlo; }
    }
    __syncthreads();

    const unsigned Ts    = R->Ts;
    const unsigned istar = R->inv_star;

    // ---- masked write-back from the smem stash ----
#pragma unroll
    for (int j = 0; j < 4; j++) {
        uint4 v = R->data[rt + j * 256];
        unsigned w4[4] = { v.x, v.y, v.z, v.w };
        unsigned o[4];
#pragma unroll
        for (int c = 0; c < 4; c++) {
            const unsigned s   = w4[c] << 1;
            const unsigned inv = invbase - (unsigned)((j << 10) + c);
            const bool keep = (s > Ts) || (s == Ts && inv >= istar);
            o[c] = keep ? w4[c] : 0u;
        }
        uint4 ov; ov.x = o[0]; ov.y = o[1]; ov.z = o[2]; ov.w = o[3];
        yout[rt + j * 256] = ov;
    }
}

extern "C" void kernel_launch(void* const* d_in, const int* in_sizes, int n_in,
                              void* d_out, int out_size) {
    const float* x = (const float*)d_in[0];
    float* y = (float*)d_out;
    const int nrows = in_sizes[0] / HW;   // 16384 rows of 4096
    topk_sparse_kernel<<<nrows / 2, NTHREAD>>>(x, y);
}

// round 13
// speedup vs baseline: 1.1655x; 1.1655x over previous
#include <cuda_runtime.h>
#include <cstdint>
#include <cstddef>

#define FULLMASK 0xFFFFFFFFu

namespace {
constexpr int      HW      = 4096;   // 64*64
constexpr unsigned KSEL    = 409;    // int(0.1 * 4096)
constexpr int      NTHREAD = 256;
constexpr int      NWARP   = 8;
constexpr int      TCAP    = 64;     // tie-list capacity for the selected bin
// Integer bins of width 2^14 over the magnitude key s = u<<1 (sign shifted out),
// covering |x| in [1.5, 1.75):
//   bm1 = (s >> 14) - (BINBASE+1);  counted bins are hist[1..255].
// "bin 0"  <=> |x| < 1.50024  -- uncounted; ~6 sigma below the 409th |x| of N(0,1)
// |x|>=1.75 -- counted in REGISTERS (c_hi), no atomics; threshold >= 1.75 is
//              ~4.6 sigma -> exact fallback if it happens.
// Boundaries are exact in key space: membership test is s - slo < 2^14.
constexpr int      BINBASE = 130560;      // 0x7F800000 >> 14
constexpr unsigned S_HI    = 0x7FC00000u; // key(1.75f) = bits(1.75)<<1
}

struct SmemT {
    uint4    data[HW / 4];   // 16KB row stash (threads read only their own words)
    unsigned hist[256];
    unsigned wsum[NWARP];
    unsigned whi[NWARP];     // per-warp totals of c_hi (elements >= 1.75)
    unsigned tcnt;
    unsigned sel;       // selected bin (0xFFFFFFFF = none)
    unsigned r2;        // rank within selected bin
    unsigned fbflag;    // 1 if chitot >= KSEL (threshold >= 1.75)
    unsigned Ts;        // threshold key (|x| bits << 1)
    unsigned inv_star;  // inverted-index cutoff for exact ties
    unsigned ts_[TCAP];
    unsigned tinv[TCAP];
};

// Block-wide total of per-thread count c (broadcast). Fallback path only.
__device__ __forceinline__ unsigned blk_total(SmemT* sm, unsigned c, int lane, int wid) {
    c = __reduce_add_sync(FULLMASK, c);
    __syncthreads();               // protect wsum reuse across calls
    if (lane == 0) sm->wsum[wid] = c;
    __syncthreads();
    unsigned t = 0;
#pragma unroll
    for (int w = 0; w < NWARP; w++) t += sm->wsum[w];
    return t;
}

__global__ void __launch_bounds__(NTHREAD, 8)
topk_sparse_kernel(const float* __restrict__ x, float* __restrict__ y)
{
    __shared__ SmemT sm;
    const int tid  = threadIdx.x;
    const int lane = tid & 31;
    const int wid  = tid >> 5;
    const size_t rowbase = (size_t)blockIdx.x * (HW / 4);
    const uint4* xin  = reinterpret_cast<const uint4*>(x) + rowbase;
    uint4*       yout = reinterpret_cast<uint4*>(y) + rowbase;
    // element (j,c) at linear idx 4*tid + 1024*j + c; inv = 4095 - idx
    const unsigned invbase = 4095u - ((unsigned)tid << 2);

    // ---- load row (4 x LDG.128, front-batched for MLP), stash to smem ----
    uint4 t0 = xin[tid];
    uint4 t1 = xin[tid + 256];
    uint4 t2 = xin[tid + 512];
    uint4 t3 = xin[tid + 768];

    sm.hist[tid] = 0;
    if (tid == 0) { sm.tcnt = 0; sm.sel = 0xFFFFFFFFu; }

    sm.data[tid]       = t0;
    sm.data[tid + 256] = t1;
    sm.data[tid + 512] = t2;
    sm.data[tid + 768] = t3;
    __syncthreads();   // hist zeros visible before atomics

    // ---- histogram pass from in-flight registers; upper tail in registers ----
    {
        unsigned uu[16] = { t0.x, t0.y, t0.z, t0.w,  t1.x, t1.y, t1.z, t1.w,
                            t2.x, t2.y, t2.z, t2.w,  t3.x, t3.y, t3.z, t3.w };
        unsigned c_hi = 0;
#pragma unroll
        for (int e = 0; e < 16; e++) {
            unsigned s = uu[e] << 1;
            c_hi += (s >= S_HI) ? 1u : 0u;                 // register-side tail count
            unsigned bm1 = (s >> 14) - (unsigned)(BINBASE + 1);
            if (bm1 < 255u)                                 // bin in [1,255]
                atomicAdd(&sm.hist[bm1 + 1u], 1u);          // fire-and-forget ATOMS
        }
        c_hi = __reduce_add_sync(FULLMASK, c_hi);
        if (lane == 0) sm.whi[wid] = c_hi;
    }
    __syncthreads();

    // ---- bin selection on WARP 0 ONLY (warps 1-7 go straight to the barrier) ----
    if (wid == 0) {
        unsigned chitot = 0;
#pragma unroll
        for (int w = 0; w < NWARP; w++) chitot += sm.whi[w];
        const bool fbhi = (chitot >= KSEL);      // threshold >= 1.75: fallback
        const unsigned r = KSEL - chitot;        // rank within [1.5, 1.75) bins

        // lane owns 8 consecutive bins in DESCENDING order:
        // descending position g = lane*8 + i  ->  bin b = 255 - g
        unsigned cnt[8];
        unsigned lsum = 0;
#pragma unroll
        for (int i = 0; i < 8; i++) {
            int b = 255 - (lane * 8 + i);
            cnt[i] = (b >= 1) ? sm.hist[b] : 0u;   // bin 0 uncounted by design
            lsum += cnt[i];
        }
        // exclusive prefix over lanes (ascending lane = descending bins)
        unsigned incl = lsum;
#pragma unroll
        for (int d = 1; d < 32; d <<= 1) {
            unsigned n = __shfl_up_sync(FULLMASK, incl, d);
            if (lane >= d) incl += n;
        }
        unsigned run = incl - lsum;
        // sequential walk inside the lane's chunk: at most one (lane,i) crosses r
#pragma unroll
        for (int i = 0; i < 8; i++) {
            unsigned nrun = run + cnt[i];
            if (!fbhi && run < r && r <= nrun) {
                sm.sel = (unsigned)(255 - (lane * 8 + i));
                sm.r2  = r - run;
            }
            run = nrun;
        }
        if (lane == 0) sm.fbflag = fbhi ? 1u : 0u;
    }
    __syncthreads();

    // ---- retrieval: 2-op range test against the selected bin's key range ----
    // (if sel is invalid, slo is garbage but fb is taken and pushes are unused)
    const unsigned slo = (sm.sel + (unsigned)BINBASE) << 14;
#pragma unroll
    for (int j = 0; j < 4; j++) {
        uint4 v = sm.data[tid + j * 256];
        unsigned w4[4] = { v.x, v.y, v.z, v.w };
#pragma unroll
        for (int c = 0; c < 4; c++) {
            unsigned s = w4[c] << 1;
            if (s - slo < (1u << 14)) {            // exact bin membership
                unsigned pos = atomicAdd(&sm.tcnt, 1u);
                if (pos < (unsigned)TCAP) {
                    sm.ts_[pos]  = s;
                    sm.tinv[pos] = invbase - (unsigned)((j << 10) + c);
                }
            }
        }
    }
    __syncthreads();

    const bool fb = (sm.fbflag != 0u) || (sm.sel == 0xFFFFFFFFu) ||
                    (sm.tcnt > (unsigned)TCAP);
    if (!fb) {
        // ---- exact selection of rank r2 within the bin (ties by index) ----
        const unsigned m2 = sm.tcnt;
        const unsigned r2 = sm.r2;
        if ((unsigned)tid < m2) {
            unsigned si = sm.ts_[tid], vi = sm.tinv[tid];
            unsigned rank = 0;
            for (unsigned j = 0; j < m2; j++) {
                unsigned sj = sm.ts_[j], vj = sm.tinv[j];
                rank += (sj > si || (sj == si && vj > vi)) ? 1u : 0u;
            }
            if (rank == r2 - 1u) { sm.Ts = si; sm.inv_star = vi; }
        }
    } else {
        // ---- exact fallback: bitwise binary search (block-uniform, reads stash) ----
        unsigned lo = 0;                       // s values are even; bit0 skipped
        for (int bit = 31; bit >= 1; bit--) {
            unsigned T = lo | (1u << bit);
            unsigned c = 0;
            for (int j = 0; j < 4; j++) {
                uint4 v = sm.data[tid + j * 256];
                c += ((v.x << 1) >= T) + ((v.y << 1) >= T) + ((v.z << 1) >= T) + ((v.w << 1) >= T);
            }
            if (blk_total(&sm, c, lane, wid) >= KSEL) lo = T;
        }
        const unsigned Tsf = lo;               // exact KSEL-th largest key
        unsigned cgt = 0;
        for (int j = 0; j < 4; j++) {
            uint4 v = sm.data[tid + j * 256];
            cgt += ((v.x << 1) > Tsf) + ((v.y << 1) > Tsf) + ((v.z << 1) > Tsf) + ((v.w << 1) > Tsf);
        }
        cgt = blk_total(&sm, cgt, lane, wid);
        const unsigned req = KSEL - cgt;       // >= 1 by construction
        unsigned vlo = 0;
        for (int bit = 11; bit >= 0; bit--) {
            unsigned V = vlo | (1u << bit);
            unsigned c = 0;
            for (int j = 0; j < 4; j++) {
                uint4 v = sm.data[tid + j * 256];
                unsigned w4[4] = { v.x, v.y, v.z, v.w };
                for (int cc = 0; cc < 4; cc++) {
                    unsigned inv = invbase - (unsigned)((j << 10) + cc);
                    c += (((w4[cc] << 1) == Tsf) && inv >= V) ? 1u : 0u;
                }
            }
            if (blk_total(&sm, c, lane, wid) >= req) vlo = V;
        }
        if (tid == 0) { sm.Ts = Tsf; sm.inv_star = vlo; }
    }
    __syncthreads();

    const unsigned Ts    = sm.Ts;
    const unsigned istar = sm.inv_star;

    // ---- masked write-back from the smem stash ----
#pragma unroll
    for (int j = 0; j < 4; j++) {
        uint4 v = sm.data[tid + j * 256];
        unsigned w4[4] = { v.x, v.y, v.z, v.w };
        unsigned o[4];
#pragma unroll
        for (int c = 0; c < 4; c++) {
            const unsigned s   = w4[c] << 1;
            const unsigned inv = invbase - (unsigned)((j << 10) + c);
            const bool keep = (s > Ts) || (s == Ts && inv >= istar);
            o[c] = keep ? w4[c] : 0u;
        }
        uint4 ov; ov.x = o[0]; ov.y = o[1]; ov.z = o[2]; ov.w = o[3];
        yout[tid + j * 256] = ov;
    }
}

extern "C" void kernel_launch(void* const* d_in, const int* in_sizes, int n_in,
                              void* d_out, int out_size) {
    const float* x = (const float*)d_in[0];
    float* y = (float*)d_out;
    const int nrows = in_sizes[0] / HW;   // 16384 rows of 4096
    topk_sparse_kernel<<<nrows, NTHREAD>>>(x, y);
}

// round 14
// speedup vs baseline: 1.2297x; 1.0551x over previous
#include <cuda_runtime.h>
#include <cstdint>
#include <cstddef>

#define FULLMASK 0xFFFFFFFFu

namespace {
constexpr int      HW      = 4096;   // 64*64
constexpr unsigned KSEL    = 409;    // int(0.1 * 4096)
constexpr int      NTHREAD = 256;
constexpr int      NWARP   = 8;
constexpr int      TCAP    = 64;     // tie-list capacity for the selected bin
// Integer bins of width 2^14 over the magnitude key s = u<<1 (sign shifted out),
// covering |x| in [1.5, 1.75):
//   bm1 = (s >> 14) - (BINBASE+1);  counted bins are hist[1..255].
// "bin 0"  <=> |x| < 1.50024  -- uncounted; ~6 sigma below the 409th |x| of N(0,1)
// |x|>=1.75 -- counted in REGISTERS (c_hi), no atomics; threshold >= 1.75 is
//              ~4.6 sigma -> exact fallback if it happens.
// Boundaries are exact in key space: membership test is s - slo < 2^14.
constexpr int      BINBASE = 130560;      // 0x7F800000 >> 14
constexpr unsigned S_HI    = 0x7FC00000u; // key(1.75f) = bits(1.75)<<1
}

struct SmemT {
    uint4    data[HW / 4];   // 16KB row stash (threads read only their own words)
    unsigned hist[256];
    unsigned wsum[NWARP];
    unsigned whi[NWARP];     // per-warp totals of c_hi (elements >= 1.75)
    unsigned tcnt;
    unsigned sel;       // selected bin (0xFFFFFFFF = none)
    unsigned r2;        // rank within selected bin
    unsigned fbflag;    // 1 if chitot >= KSEL (threshold >= 1.75)
    unsigned Ts;        // threshold key (|x| bits << 1)
    unsigned inv_star;  // (fallback only) tie cutoff
    unsigned tu[TCAP];  // candidate ORIGINAL words
    unsigned tinv[TCAP];
};

// Block-wide total of per-thread count c (broadcast). Fallback path only.
__device__ __forceinline__ unsigned blk_total(SmemT* sm, unsigned c, int lane, int wid) {
    c = __reduce_add_sync(FULLMASK, c);
    __syncthreads();               // protect wsum reuse across calls
    if (lane == 0) sm->wsum[wid] = c;
    __syncthreads();
    unsigned t = 0;
#pragma unroll
    for (int w = 0; w < NWARP; w++) t += sm->wsum[w];
    return t;
}

__global__ void __launch_bounds__(NTHREAD, 8)
topk_sparse_kernel(const float* __restrict__ x, float* __restrict__ y)
{
    __shared__ SmemT sm;
    const int tid  = threadIdx.x;
    const int lane = tid & 31;
    const int wid  = tid >> 5;
    const size_t rowbase = (size_t)blockIdx.x * (HW / 4);
    const uint4* xin  = reinterpret_cast<const uint4*>(x) + rowbase;
    uint4*       yout = reinterpret_cast<uint4*>(y) + rowbase;
    // element (j,c) at linear idx 4*tid + 1024*j + c; inv = 4095 - idx
    const unsigned invbase = 4095u - ((unsigned)tid << 2);

    // ---- load row (4 x LDG.128, front-batched for MLP), stash to smem ----
    uint4 t0 = xin[tid];
    uint4 t1 = xin[tid + 256];
    uint4 t2 = xin[tid + 512];
    uint4 t3 = xin[tid + 768];

    sm.hist[tid] = 0;
    if (tid == 0) { sm.tcnt = 0; sm.sel = 0xFFFFFFFFu; }

    sm.data[tid]       = t0;
    sm.data[tid + 256] = t1;
    sm.data[tid + 512] = t2;
    sm.data[tid + 768] = t3;
    __syncthreads();   // hist zeros visible before atomics

    // ---- histogram pass from in-flight registers; upper tail in registers ----
    {
        unsigned uu[16] = { t0.x, t0.y, t0.z, t0.w,  t1.x, t1.y, t1.z, t1.w,
                            t2.x, t2.y, t2.z, t2.w,  t3.x, t3.y, t3.z, t3.w };
        unsigned c_hi = 0;
#pragma unroll
        for (int e = 0; e < 16; e++) {
            unsigned s = uu[e] << 1;
            c_hi += (s >= S_HI) ? 1u : 0u;                 // register-side tail count
            unsigned bm1 = (s >> 14) - (unsigned)(BINBASE + 1);
            if (bm1 < 255u)                                 // bin in [1,255]
                atomicAdd(&sm.hist[bm1 + 1u], 1u);          // fire-and-forget ATOMS
        }
        c_hi = __reduce_add_sync(FULLMASK, c_hi);
        if (lane == 0) sm.whi[wid] = c_hi;
    }
    __syncthreads();

    // ---- bin selection on WARP 0 ONLY (warps 1-7 go straight to the barrier) ----
    if (wid == 0) {
        unsigned chitot = 0;
#pragma unroll
        for (int w = 0; w < NWARP; w++) chitot += sm.whi[w];
        const bool fbhi = (chitot >= KSEL);      // threshold >= 1.75: fallback
        const unsigned r = KSEL - chitot;        // rank within [1.5, 1.75) bins

        // lane owns 8 consecutive bins in DESCENDING order:
        // descending position g = lane*8 + i  ->  bin b = 255 - g
        unsigned cnt[8];
        unsigned lsum = 0;
#pragma unroll
        for (int i = 0; i < 8; i++) {
            int b = 255 - (lane * 8 + i);
            cnt[i] = (b >= 1) ? sm.hist[b] : 0u;   // bin 0 uncounted by design
            lsum += cnt[i];
        }
        // exclusive prefix over lanes (ascending lane = descending bins)
        unsigned incl = lsum;
#pragma unroll
        for (int d = 1; d < 32; d <<= 1) {
            unsigned n = __shfl_up_sync(FULLMASK, incl, d);
            if (lane >= d) incl += n;
        }
        unsigned run = incl - lsum;
        // sequential walk inside the lane's chunk: at most one (lane,i) crosses r
#pragma unroll
        for (int i = 0; i < 8; i++) {
            unsigned nrun = run + cnt[i];
            if (!fbhi && run < r && r <= nrun) {
                sm.sel = (unsigned)(255 - (lane * 8 + i));
                sm.r2  = r - run;
            }
            run = nrun;
        }
        if (lane == 0) sm.fbflag = fbhi ? 1u : 0u;
    }
    __syncthreads();

    // ---- retrieval: 2-op range test against the selected bin's key range ----
    // (if sel is invalid, slo is garbage but fb is taken and pushes are unused)
    const unsigned slo = (sm.sel + (unsigned)BINBASE) << 14;
#pragma unroll
    for (int j = 0; j < 4; j++) {
        uint4 v = sm.data[tid + j * 256];
        unsigned w4[4] = { v.x, v.y, v.z, v.w };
#pragma unroll
        for (int c = 0; c < 4; c++) {
            unsigned s = w4[c] << 1;
            if (s - slo < (1u << 14)) {            // exact bin membership
                unsigned pos = atomicAdd(&sm.tcnt, 1u);
                if (pos < (unsigned)TCAP) {
                    sm.tu[pos]   = w4[c];          // original word (sign intact)
                    sm.tinv[pos] = invbase - (unsigned)((j << 10) + c);
                }
            }
        }
    }
    __syncthreads();

    const bool fb = (sm.fbflag != 0u) || (sm.sel == 0xFFFFFFFFu) ||
                    (sm.tcnt > (unsigned)TCAP);

    // per-candidate state carried across the writeback barrier
    bool     cand_keep = false;
    unsigned cand_u = 0, cand_inv = 0;

    if (!fb) {
        // ---- tie resolution among candidates; publish Ts (rank r2-1 key) ----
        const unsigned m2 = sm.tcnt;
        const unsigned r2 = sm.r2;
        if ((unsigned)tid < m2) {
            unsigned ui = sm.tu[tid], vi = sm.tinv[tid];
            unsigned si = ui << 1;
            unsigned rank = 0;
            for (unsigned j = 0; j < m2; j++) {
                unsigned sj = sm.tu[j] << 1, vj = sm.tinv[j];
                rank += (sj > si || (sj == si && vj > vi)) ? 1u : 0u;
            }
            if (rank == r2 - 1u) sm.Ts = si;       // exact KSEL-th largest key
            cand_keep = (rank < r2);
            cand_u = ui; cand_inv = vi;
        }
        __syncthreads();   // Ts visible to all

        const unsigned Ts = sm.Ts;
        // ---- bulk writeback: strictly-above-threshold only (3 ops/elem);
        //      ties provisionally zeroed, restored by candidates below ----
#pragma unroll
        for (int j = 0; j < 4; j++) {
            uint4 v = sm.data[tid + j * 256];
            unsigned o0 = ((v.x << 1) > Ts) ? v.x : 0u;
            unsigned o1 = ((v.y << 1) > Ts) ? v.y : 0u;
            unsigned o2 = ((v.z << 1) > Ts) ? v.z : 0u;
            unsigned o3 = ((v.w << 1) > Ts) ? v.w : 0u;
            uint4 ov; ov.x = o0; ov.y = o1; ov.z = o2; ov.w = o3;
            yout[tid + j * 256] = ov;
        }
        __syncthreads();   // order bulk STGs before candidate fixup STGs

        // ---- tie fixup: kept candidates restore their word (scalar STG) ----
        if (cand_keep) {
            unsigned idx = 4095u - cand_inv;
            reinterpret_cast<unsigned*>(yout)[idx] = cand_u;
        }
    } else {
        // ---- exact fallback: bitwise binary search (block-uniform, reads stash) ----
        unsigned lo = 0;                       // s values are even; bit0 skipped
        for (int bit = 31; bit >= 1; bit--) {
            unsigned T = lo | (1u << bit);
            unsigned c = 0;
            for (int j = 0; j < 4; j++) {
                uint4 v = sm.data[tid + j * 256];
                c += ((v.x << 1) >= T) + ((v.y << 1) >= T) + ((v.z << 1) >= T) + ((v.w << 1) >= T);
            }
            if (blk_total(&sm, c, lane, wid) >= KSEL) lo = T;
        }
        const unsigned Tsf = lo;               // exact KSEL-th largest key
        unsigned cgt = 0;
        for (int j = 0; j < 4; j++) {
            uint4 v = sm.data[tid + j * 256];
            cgt += ((v.x << 1) > Tsf) + ((v.y << 1) > Tsf) + ((v.z << 1) > Tsf) + ((v.w << 1) > Tsf);
        }
        cgt = blk_total(&sm, cgt, lane, wid);
        const unsigned req = KSEL - cgt;       // >= 1 by construction
        unsigned vlo = 0;
        for (int bit = 11; bit >= 0; bit--) {
            unsigned V = vlo | (1u << bit);
            unsigned c = 0;
            for (int j = 0; j < 4; j++) {
                uint4 v = sm.data[tid + j * 256];
                unsigned w4[4] = { v.x, v.y, v.z, v.w };
                for (int cc = 0; cc < 4; cc++) {
                    unsigned inv = invbase - (unsigned)((j << 10) + cc);
                    c += (((w4[cc] << 1) == Tsf) && inv >= V) ? 1u : 0u;
                }
            }
            if (blk_total(&sm, c, lane, wid) >= req) vlo = V;
        }
        if (tid == 0) { sm.Ts = Tsf; sm.inv_star = vlo; }
        __syncthreads();
        const unsigned Ts    = sm.Ts;
        const unsigned istar = sm.inv_star;
        // full exact writeback (rare path)
#pragma unroll
        for (int j = 0; j < 4; j++) {
            uint4 v = sm.data[tid + j * 256];
            unsigned w4[4] = { v.x, v.y, v.z, v.w };
            unsigned o[4];
#pragma unroll
            for (int c = 0; c < 4; c++) {
                const unsigned s   = w4[c] << 1;
                const unsigned inv = invbase - (unsigned)((j << 10) + c);
                const bool keep = (s > Ts) || (s == Ts && inv >= istar);
                o[c] = keep ? w4[c] : 0u;
            }
            uint4 ov; ov.x = o[0]; ov.y = o[1]; ov.z = o[2]; ov.w = o[3];
            yout[tid + j * 256] = ov;
        }
    }
}

extern "C" void kernel_launch(void* const* d_in, const int* in_sizes, int n_in,
                              void* d_out, int out_size) {
    const float* x = (const float*)d_in[0];
    float* y = (float*)d_out;
    const int nrows = in_sizes[0] / HW;   // 16384 rows of 4096
    topk_sparse_kernel<<<nrows, NTHREAD>>>(x, y);
}